// round 10
// baseline (speedup 1.0000x reference)
#include <cuda_runtime.h>

// LocalAttn, 2-kernel pipeline for GB300 (sm_103a), round 10.
// Kernel A (stage1): 512 px per block, 2 pixels per thread.
//   Coalesced LDG.64 x staging into quad-swizzled smem rows; both pixel rows
//   -> registers; conv1/conv2/mn and v = wv@x with each weight LDS.128 feeding
//   4 independent fma2 (2 per pixel) -> halved weight traffic, doubled ILP.
//   v -> own swizzled smem rows -> coalesced STG -> g_v.
// Kernel M (combine): identical to round 5 (22.2us).

typedef unsigned long long ull;

__device__ float g_v [2u * 8u * 16384u * 32u];   // [img][g][px][32]  33.5 MB
__device__ float g_mn[2u * 80u * 16384u];        // [img][ch][px]     10.5 MB

__device__ __forceinline__ ull fma2(ull a, ull b, ull c) {
    ull d;
    asm("fma.rn.f32x2 %0, %1, %2, %3;" : "=l"(d) : "l"(a), "l"(b), "l"(c));
    return d;
}
__device__ __forceinline__ float hadd2(ull a) {
    float x, y;
    asm("mov.b64 {%0,%1}, %2;" : "=f"(x), "=f"(y) : "l"(a));
    return x + y;
}
__device__ __forceinline__ float ftanh(float x) {
    float e = __expf(-2.f * fabsf(x));
    float r = __fdividef(1.f - e, 1.f + e);
    return copysignf(r, x);
}

// ============================ Kernel A ============================
// grid (32, 8, 2) = (512-px chunk, group, img), block 256, 2 px per thread.
// smem x layout: word = px*36 + ((q ^ ((px>>3)&7))<<2) + w   (c = 4q + w)
__global__ __launch_bounds__(256, 2)
void stage1_kernel(
    const float* __restrict__ x,
    const float* __restrict__ w1, const float* __restrict__ b1,
    const float* __restrict__ g1, const float* __restrict__ be1,
    const float* __restrict__ m1, const float* __restrict__ v1,
    const float* __restrict__ w2, const float* __restrict__ b2,
    const float* __restrict__ g2, const float* __restrict__ be2,
    const float* __restrict__ m2, const float* __restrict__ v2,
    const float* __restrict__ wv)
{
    extern __shared__ __align__(16) float sm[];
    float* s_px  = sm;               // 512*36 swizzled [px][ci]; later v
    float* s_w1g = sm + 18432;       // 256
    float* s_wvg = s_w1g + 256;      // 1024
    float* s_w2g = s_wvg + 1024;     // 80
    float* s_a1  = s_w2g + 80;       // 8
    float* s_c1  = s_a1 + 8;         // 8
    float* s_a2  = s_c1 + 8;         // 10
    float* s_c2  = s_a2 + 10;        // 10

    const int t    = threadIdx.x;
    const int lane = t & 31;
    const int wq   = t >> 5;
    const int px0  = blockIdx.x * 512;
    const int g    = blockIdx.y;
    const int img  = blockIdx.z;

    // weights + folded BN params
    s_w1g[t] = w1[g * 256 + t];
    for (int i = t; i < 1024; i += 256) s_wvg[i] = wv[g * 1024 + i];
    if (t < 80) s_w2g[t] = w2[g * 80 + t];
    if (t < 8) {
        int ch = g * 8 + t;
        float inv = g1[ch] * rsqrtf(v1[ch] + 1e-5f);
        s_a1[t] = inv;
        s_c1[t] = b1[ch] * inv + be1[ch] - m1[ch] * inv;
    } else if (t >= 32 && t < 42) {
        int o = t - 32, ch = g * 10 + o;
        float inv = g2[ch] * rsqrtf(v2[ch] + 1e-5f);
        s_a2[o] = inv;
        s_c2[o] = b2[ch] * inv + be2[ch] - m2[ch] * inv;
    }

    // ---- coalesced x staging: warp wq handles channels [wq*4, wq*4+4) ----
    {
        const float* xg = x + ((size_t)img * 256 + g * 32) * 16384 + px0;
        #pragma unroll
        for (int it = 0; it < 4; ++it) {
            int c = wq * 4 + it;
            int q = c >> 2, wrd = c & 3;
            const float* src = xg + (size_t)c * 16384;
            #pragma unroll
            for (int seg = 0; seg < 8; ++seg) {
                int p = (lane + seg * 32) * 2;           // even pixel 0..510
                float2 v2 = *(const float2*)(src + p);
                int qs = ((q ^ ((p >> 3) & 7)) << 2) + wrd;
                s_px[p * 36 + qs]       = v2.x;
                s_px[(p + 1) * 36 + qs] = v2.y;
            }
        }
    }
    __syncthreads();

    // pull both x rows into registers (logical quad order, physical swizzled)
    const int pA = t, pB = t + 256;
    const int swA = (pA >> 3) & 7, swB = (pB >> 3) & 7;
    float* rowA = s_px + pA * 36;
    float* rowB = s_px + pB * 36;
    ulonglong2 xa[8], xb[8];
    #pragma unroll
    for (int q = 0; q < 8; q++) {
        xa[q] = *(const ulonglong2*)(rowA + ((q ^ swA) << 2));
        xb[q] = *(const ulonglong2*)(rowB + ((q ^ swB) << 2));
    }

    // ---- conv1 -> bn -> tanh -> conv2 -> bn -> g_mn (both pixels) ----
    {
        ull accA[8], accB[8];
        #pragma unroll
        for (int o = 0; o < 8; o++) { accA[o] = 0ULL; accB[o] = 0ULL; }
        #pragma unroll
        for (int q = 0; q < 8; q++) {
            #pragma unroll
            for (int o = 0; o < 8; o++) {
                ulonglong2 wp = *(const ulonglong2*)(s_w1g + o * 32 + q * 4);
                accA[o] = fma2(xa[q].x, wp.x, accA[o]);
                accB[o] = fma2(xb[q].x, wp.x, accB[o]);
                accA[o] = fma2(xa[q].y, wp.y, accA[o]);
                accB[o] = fma2(xb[q].y, wp.y, accB[o]);
            }
        }
        float tvA[8], tvB[8];
        #pragma unroll
        for (int o = 0; o < 8; o++) {
            tvA[o] = ftanh(hadd2(accA[o]) * s_a1[o] + s_c1[o]);
            tvB[o] = ftanh(hadd2(accB[o]) * s_a1[o] + s_c1[o]);
        }

        float* mb = g_mn + ((size_t)img * 80 + g * 10) * 16384 + px0 + t;
        #pragma unroll
        for (int o2 = 0; o2 < 10; o2++) {
            float aA = 0.f, aB = 0.f;
            #pragma unroll
            for (int o = 0; o < 8; o++) {
                float wv2 = s_w2g[o2 * 8 + o];
                aA += tvA[o] * wv2;
                aB += tvB[o] * wv2;
            }
            mb[(size_t)o2 * 16384]       = aA * s_a2[o2] + s_c2[o2];
            mb[(size_t)o2 * 16384 + 256] = aB * s_a2[o2] + s_c2[o2];
        }
    }

    // ---- v = wv @ x: 4 chunks of 8 outputs, both pixels per weight load ----
    #pragma unroll
    for (int ch = 0; ch < 4; ch++) {
        ull accA[8], accB[8];
        #pragma unroll
        for (int o = 0; o < 8; o++) { accA[o] = 0ULL; accB[o] = 0ULL; }
        #pragma unroll
        for (int q = 0; q < 8; q++) {
            #pragma unroll
            for (int o = 0; o < 8; o++) {
                ulonglong2 wp = *(const ulonglong2*)(s_wvg + (ch * 8 + o) * 32 + q * 4);
                accA[o] = fma2(xa[q].x, wp.x, accA[o]);
                accB[o] = fma2(xb[q].x, wp.x, accB[o]);
                accA[o] = fma2(xa[q].y, wp.y, accA[o]);
                accB[o] = fma2(xb[q].y, wp.y, accB[o]);
            }
        }
        float4 r;
        r.x = hadd2(accA[0]); r.y = hadd2(accA[1]);
        r.z = hadd2(accA[2]); r.w = hadd2(accA[3]);
        *(float4*)(rowA + (((2 * ch)     ^ swA) << 2)) = r;
        r.x = hadd2(accA[4]); r.y = hadd2(accA[5]);
        r.z = hadd2(accA[6]); r.w = hadd2(accA[7]);
        *(float4*)(rowA + (((2 * ch + 1) ^ swA) << 2)) = r;
        r.x = hadd2(accB[0]); r.y = hadd2(accB[1]);
        r.z = hadd2(accB[2]); r.w = hadd2(accB[3]);
        *(float4*)(rowB + (((2 * ch)     ^ swB) << 2)) = r;
        r.x = hadd2(accB[4]); r.y = hadd2(accB[5]);
        r.z = hadd2(accB[6]); r.w = hadd2(accB[7]);
        *(float4*)(rowB + (((2 * ch + 1) ^ swB) << 2)) = r;
    }
    __syncthreads();

    // ---- coalesced store of v: warp writes 512B contiguous ----
    float* vplane = g_v + ((size_t)(img * 8 + g) * 16384 + px0) * 32;
    #pragma unroll
    for (int i = 0; i < 16; i++) {
        int idx = t + i * 256;          // 4096 float4 items
        int p = idx >> 3, q = idx & 7;
        int sp = (p >> 3) & 7;
        float4 v4 = *(const float4*)(s_px + p * 36 + ((q ^ sp) << 2));
        *(float4*)(vplane + p * 32 + q * 4) = v4;
    }
}

// ============================ Kernel M ============================
// grid (8, 8, 16): z = img*8 + g. block 256 (one thread per center pixel).
__global__ __launch_bounds__(256, 4)
void combine_kernel(float* __restrict__ out)
{
    __shared__ __align__(16) float s_v[324 * 36];   // [hp][co] pitch 36

    const int t   = threadIdx.x;
    const int ty  = t >> 4, tx = t & 15;
    const int w0  = blockIdx.x * 16;
    const int h0  = blockIdx.y * 16;
    const int img = blockIdx.z >> 3;
    const int g   = blockIdx.z & 7;
    const int h   = h0 + ty, w = w0 + tx;
    const int px  = h * 128 + w;

    // ---- v halo gather first (overlap L2 latency with scalar work) ----
    const float* vt = g_v + (size_t)(img * 8 + g) * (16384u * 32u);
    #pragma unroll
    for (int i = 0; i < 11; i++) {
        int idx = t + i * 256;
        if (idx < 2592) {
            int hp = idx >> 3, q = idx & 7;
            int hy = hp / 18, hx = hp - hy * 18;
            int hh = h0 + hy - 1, ww = w0 + hx - 1;
            float4 v4 = make_float4(0.f, 0.f, 0.f, 0.f);
            if (((unsigned)hh < 128u) & ((unsigned)ww < 128u))
                v4 = *(const float4*)(vt + (size_t)(hh * 128 + ww) * 32 + q * 4);
            *(float4*)(s_v + hp * 36 + q * 4) = v4;
        }
    }

    // ---- logits: mask (9 strided coalesced) + neighbor (9 predicated) ----
    float a[9];
    {
        const float* nbg   = g_mn + ((size_t)img * 80 + g) * 16384;
        const float* mbase = g_mn + ((size_t)img * 80 + 8 + g * 9) * 16384 + px;
        #pragma unroll
        for (int k = 0; k < 9; k++) {
            int i = k / 3, j = k - i * 3;
            int hh = h + i - 1, ww = w + j - 1;
            float nb = 0.f;
            if (((unsigned)hh < 128u) & ((unsigned)ww < 128u))
                nb = nbg[hh * 128 + ww];
            a[k] = mbase[(size_t)k * 16384] + nb;
        }
        float mx = a[0];
        #pragma unroll
        for (int k = 1; k < 9; k++) mx = fmaxf(mx, a[k]);
        float s = 0.f;
        #pragma unroll
        for (int k = 0; k < 9; k++) { a[k] = __expf(a[k] - mx); s += a[k]; }
        float inv = 1.f / s;
        #pragma unroll
        for (int k = 0; k < 9; k++) a[k] *= inv;
    }
    __syncthreads();

    // ---- combine: out[c] = sum_k a[k] * v[c] at neighbor k ----
    {
        int hpk[9];
        #pragma unroll
        for (int k = 0; k < 9; k++) {
            int i = k / 3, j = k - i * 3;
            hpk[k] = ((ty + i) * 18 + (tx + j)) * 36;
        }
        float* ob = out + ((size_t)img * 256 + g * 32) * 16384 + px;
        #pragma unroll
        for (int c4 = 0; c4 < 8; c4++) {
            float ax = 0.f, ay = 0.f, az = 0.f, aw = 0.f;
            #pragma unroll
            for (int k = 0; k < 9; k++) {
                float4 vv = *(const float4*)(s_v + hpk[k] + c4 * 4);
                ax += a[k] * vv.x; ay += a[k] * vv.y;
                az += a[k] * vv.z; aw += a[k] * vv.w;
            }
            ob[(size_t)(c4 * 4 + 0) * 16384] = ax;
            ob[(size_t)(c4 * 4 + 1) * 16384] = ay;
            ob[(size_t)(c4 * 4 + 2) * 16384] = az;
            ob[(size_t)(c4 * 4 + 3) * 16384] = aw;
        }
    }
}

static const int A_SMEM = (18432 + 256 + 1024 + 80 + 8 + 8 + 10 + 10) * 4;  // 79.3 KB

extern "C" void kernel_launch(void* const* d_in, const int* in_sizes, int n_in,
                              void* d_out, int out_size) {
    const float* x   = (const float*)d_in[0];
    const float* w1  = (const float*)d_in[1];
    const float* b1  = (const float*)d_in[2];
    const float* g1  = (const float*)d_in[3];
    const float* be1 = (const float*)d_in[4];
    const float* m1  = (const float*)d_in[5];
    const float* v1  = (const float*)d_in[6];
    const float* w2  = (const float*)d_in[7];
    const float* b2  = (const float*)d_in[8];
    const float* g2  = (const float*)d_in[9];
    const float* be2 = (const float*)d_in[10];
    const float* m2  = (const float*)d_in[11];
    const float* v2  = (const float*)d_in[12];
    const float* wv  = (const float*)d_in[13];
    float* out = (float*)d_out;

    static int inited = 0;
    if (!inited) {
        cudaFuncSetAttribute(stage1_kernel,
                             cudaFuncAttributeMaxDynamicSharedMemorySize, A_SMEM);
        inited = 1;
    }

    stage1_kernel<<<dim3(32, 8, 2), 256, A_SMEM>>>(x, w1, b1, g1, be1, m1, v1,
                                                   w2, b2, g2, be2, m2, v2, wv);
    combine_kernel<<<dim3(8, 8, 16), 256>>>(out);
}

// round 11
// speedup vs baseline: 1.5198x; 1.5198x over previous
#include <cuda_runtime.h>
#include <cuda_fp16.h>

// LocalAttn, 2-kernel pipeline for GB300 (sm_103a), round 11.
// = round-5 structure (best so far, 55.8us) + g_v stored in fp16 (halves the
//   dominant DRAM traffic) + fast tanh in stage1.
// Kernel A (stage1): coalesced LDG.64 x staging into quad-swizzled smem rows,
//   x row -> registers, mn = bn2(conv2(ftanh(bn1(conv1 x)))) -> g_mn (fp32),
//   v = wv @ x -> own swizzled smem row -> coalesced fp16 STG -> g_v.
// Kernel M (combine): gather fp16 v halo (coalesced 16B), convert to fp32 smem,
//   softmax(mask+nb) in regs, combine, write out.

typedef unsigned long long ull;

__device__ __half g_v [2u * 8u * 16384u * 32u]; // [img][g][px][32]  16.8 MB
__device__ float  g_mn[2u * 80u * 16384u];      // [img][ch][px]     10.5 MB

__device__ __forceinline__ ull fma2(ull a, ull b, ull c) {
    ull d;
    asm("fma.rn.f32x2 %0, %1, %2, %3;" : "=l"(d) : "l"(a), "l"(b), "l"(c));
    return d;
}
__device__ __forceinline__ float hadd2(ull a) {
    float x, y;
    asm("mov.b64 {%0,%1}, %2;" : "=f"(x), "=f"(y) : "l"(a));
    return x + y;
}
__device__ __forceinline__ float ftanh(float x) {
    float e = __expf(-2.f * fabsf(x));
    float r = __fdividef(1.f - e, 1.f + e);
    return copysignf(r, x);
}

// ============================ Kernel A ============================
// grid (64, 8, 2) = (px chunk, group, img), block 256, one thread per pixel.
// smem x layout: word = px*36 + ((q ^ ((px>>3)&7))<<2) + w   (c = 4q + w)
__global__ __launch_bounds__(256, 3)
void stage1_kernel(
    const float* __restrict__ x,
    const float* __restrict__ w1, const float* __restrict__ b1,
    const float* __restrict__ g1, const float* __restrict__ be1,
    const float* __restrict__ m1, const float* __restrict__ v1,
    const float* __restrict__ w2, const float* __restrict__ b2,
    const float* __restrict__ g2, const float* __restrict__ be2,
    const float* __restrict__ m2, const float* __restrict__ v2,
    const float* __restrict__ wv)
{
    __shared__ __align__(16) float s_px[256 * 36];   // swizzled [px][ci]; later v
    __shared__ __align__(16) float s_w1g[256];       // w1[g]  (8,32)
    __shared__ __align__(16) float s_wvg[1024];      // wv[g]  (32,32)
    __shared__ __align__(16) float s_w2g[80];        // w2[g]  (10,8)
    __shared__ float s_a1[8], s_c1[8], s_a2[10], s_c2[10];

    const int t    = threadIdx.x;
    const int lane = t & 31;
    const int wq   = t >> 5;
    const int px0  = blockIdx.x * 256;
    const int g    = blockIdx.y;
    const int img  = blockIdx.z;

    // weights + folded BN params
    s_w1g[t] = w1[g * 256 + t];
    for (int i = t; i < 1024; i += 256) s_wvg[i] = wv[g * 1024 + i];
    if (t < 80) s_w2g[t] = w2[g * 80 + t];
    if (t < 8) {
        int ch = g * 8 + t;
        float inv = g1[ch] * rsqrtf(v1[ch] + 1e-5f);
        s_a1[t] = inv;
        s_c1[t] = b1[ch] * inv + be1[ch] - m1[ch] * inv;
    } else if (t >= 32 && t < 42) {
        int o = t - 32, ch = g * 10 + o;
        float inv = g2[ch] * rsqrtf(v2[ch] + 1e-5f);
        s_a2[o] = inv;
        s_c2[o] = b2[ch] * inv + be2[ch] - m2[ch] * inv;
    }

    // ---- coalesced x staging: warp wq handles channels [wq*4, wq*4+4) ----
    {
        const float* xg = x + ((size_t)img * 256 + g * 32) * 16384 + px0;
        #pragma unroll
        for (int it = 0; it < 4; ++it) {
            int c = wq * 4 + it;
            int q = c >> 2, wrd = c & 3;
            const float* src = xg + (size_t)c * 16384;
            #pragma unroll
            for (int seg = 0; seg < 4; ++seg) {
                int p = (lane + seg * 32) * 2;           // even pixel
                float2 v2 = *(const float2*)(src + p);
                int qs = ((q ^ ((p >> 3) & 7)) << 2) + wrd;
                s_px[p * 36 + qs]       = v2.x;
                s_px[(p + 1) * 36 + qs] = v2.y;
            }
        }
    }
    __syncthreads();

    // pull own x row into registers (logical quad order, physical swizzled)
    const int sw = (t >> 3) & 7;
    float* xrow = s_px + t * 36;
    ulonglong2 xr[8];
    #pragma unroll
    for (int q = 0; q < 8; q++)
        xr[q] = *(const ulonglong2*)(xrow + ((q ^ sw) << 2));

    // ---- conv1 -> bn -> tanh -> conv2 -> bn -> g_mn ----
    {
        ull acc[8];
        #pragma unroll
        for (int o = 0; o < 8; o++) acc[o] = 0ULL;
        #pragma unroll
        for (int q = 0; q < 8; q++) {
            #pragma unroll
            for (int o = 0; o < 8; o++) {
                ulonglong2 wp = *(const ulonglong2*)(s_w1g + o * 32 + q * 4);
                acc[o] = fma2(xr[q].x, wp.x, acc[o]);
                acc[o] = fma2(xr[q].y, wp.y, acc[o]);
            }
        }
        float tv[8];
        #pragma unroll
        for (int o = 0; o < 8; o++)
            tv[o] = ftanh(hadd2(acc[o]) * s_a1[o] + s_c1[o]);

        float* mb = g_mn + ((size_t)img * 80 + g * 10) * 16384 + px0 + t;
        #pragma unroll
        for (int o2 = 0; o2 < 10; o2++) {
            float a = 0.f;
            #pragma unroll
            for (int o = 0; o < 8; o++) a += tv[o] * s_w2g[o2 * 8 + o];
            mb[(size_t)o2 * 16384] = a * s_a2[o2] + s_c2[o2];
        }
    }

    // ---- v = wv @ x in 4 chunks of 8 outputs; write into own swizzled row ----
    #pragma unroll
    for (int ch = 0; ch < 4; ch++) {
        ull acc[8];
        #pragma unroll
        for (int o = 0; o < 8; o++) acc[o] = 0ULL;
        #pragma unroll
        for (int q = 0; q < 8; q++) {
            #pragma unroll
            for (int o = 0; o < 8; o++) {
                ulonglong2 wp = *(const ulonglong2*)(s_wvg + (ch * 8 + o) * 32 + q * 4);
                acc[o] = fma2(xr[q].x, wp.x, acc[o]);
                acc[o] = fma2(xr[q].y, wp.y, acc[o]);
            }
        }
        float4 r;
        r.x = hadd2(acc[0]); r.y = hadd2(acc[1]);
        r.z = hadd2(acc[2]); r.w = hadd2(acc[3]);
        *(float4*)(xrow + (((2 * ch)     ^ sw) << 2)) = r;
        r.x = hadd2(acc[4]); r.y = hadd2(acc[5]);
        r.z = hadd2(acc[6]); r.w = hadd2(acc[7]);
        *(float4*)(xrow + (((2 * ch + 1) ^ sw) << 2)) = r;
    }
    __syncthreads();

    // ---- coalesced fp16 store of v: warp writes 256B contiguous ----
    __half* vplane = g_v + ((size_t)(img * 8 + g) * 16384 + px0) * 32;
    #pragma unroll
    for (int i = 0; i < 8; i++) {
        int idx = t + i * 256;          // 2048 4-channel items
        int p = idx >> 3, q = idx & 7;
        int sp = (p >> 3) & 7;
        float4 v4 = *(const float4*)(s_px + p * 36 + ((q ^ sp) << 2));
        __half2 h0 = __floats2half2_rn(v4.x, v4.y);
        __half2 h1 = __floats2half2_rn(v4.z, v4.w);
        uint2 st;
        st.x = *(unsigned int*)&h0;
        st.y = *(unsigned int*)&h1;
        *(uint2*)(vplane + p * 32 + q * 4) = st;
    }
}

// ============================ Kernel M ============================
// grid (8, 8, 16): z = img*8 + g. block 256 (one thread per center pixel).
__global__ __launch_bounds__(256, 4)
void combine_kernel(float* __restrict__ out)
{
    __shared__ __align__(16) float s_v[324 * 36];   // [hp][co] pitch 36 (fp32)

    const int t   = threadIdx.x;
    const int ty  = t >> 4, tx = t & 15;
    const int w0  = blockIdx.x * 16;
    const int h0  = blockIdx.y * 16;
    const int img = blockIdx.z >> 3;
    const int g   = blockIdx.z & 7;
    const int h   = h0 + ty, w = w0 + tx;
    const int px  = h * 128 + w;

    // ---- v halo gather (fp16, 16B loads = 8 channels) ----
    const __half* vt = g_v + (size_t)(img * 8 + g) * (16384u * 32u);
    #pragma unroll
    for (int i = 0; i < 6; i++) {
        int idx = t + i * 256;          // 1296 items = 324 px * 4 chunks
        if (idx < 1296) {
            int hp = idx >> 2, q = idx & 3;
            int hy = hp / 18, hx = hp - hy * 18;
            int hh = h0 + hy - 1, ww = w0 + hx - 1;
            uint2 raw = make_uint2(0u, 0u);
            if (((unsigned)hh < 128u) & ((unsigned)ww < 128u))
                raw = *(const uint2*)(vt + (size_t)(hh * 128 + ww) * 32 + q * 8);
            __half2 h0v = *(__half2*)&raw.x;
            __half2 h1v = *(__half2*)&raw.y;
            float2 f0 = __half22float2(h0v);
            float2 f1 = __half22float2(h1v);
            float* dst = s_v + hp * 36 + q * 8;
            // note: q*8 covers halves [q*8, q*8+4); second uint of raw gives +2..3
            dst[0] = f0.x; dst[1] = f0.y; dst[2] = f1.x; dst[3] = f1.y;
            // next 4 halves of this 16B load:
            // (16B = 8 halves) -> load upper 8B too via a second uint2? No:
            // uint2 is only 8B = 4 halves. Use a second load for the next 4.
        }
    }
    // second half of each 8-half chunk handled by loading uint2 at +4 halves
    #pragma unroll
    for (int i = 0; i < 6; i++) {
        int idx = t + i * 256;
        if (idx < 1296) {
            int hp = idx >> 2, q = idx & 3;
            int hy = hp / 18, hx = hp - hy * 18;
            int hh = h0 + hy - 1, ww = w0 + hx - 1;
            uint2 raw = make_uint2(0u, 0u);
            if (((unsigned)hh < 128u) & ((unsigned)ww < 128u))
                raw = *(const uint2*)(vt + (size_t)(hh * 128 + ww) * 32 + q * 8 + 4);
            __half2 h0v = *(__half2*)&raw.x;
            __half2 h1v = *(__half2*)&raw.y;
            float2 f0 = __half22float2(h0v);
            float2 f1 = __half22float2(h1v);
            float* dst = s_v + hp * 36 + q * 8 + 4;
            dst[0] = f0.x; dst[1] = f0.y; dst[2] = f1.x; dst[3] = f1.y;
        }
    }

    // ---- logits: mask (9 strided coalesced) + neighbor (9 predicated) ----
    float a[9];
    {
        const float* nbg   = g_mn + ((size_t)img * 80 + g) * 16384;
        const float* mbase = g_mn + ((size_t)img * 80 + 8 + g * 9) * 16384 + px;
        #pragma unroll
        for (int k = 0; k < 9; k++) {
            int i = k / 3, j = k - i * 3;
            int hh = h + i - 1, ww = w + j - 1;
            float nb = 0.f;
            if (((unsigned)hh < 128u) & ((unsigned)ww < 128u))
                nb = nbg[hh * 128 + ww];
            a[k] = mbase[(size_t)k * 16384] + nb;
        }
        float mx = a[0];
        #pragma unroll
        for (int k = 1; k < 9; k++) mx = fmaxf(mx, a[k]);
        float s = 0.f;
        #pragma unroll
        for (int k = 0; k < 9; k++) { a[k] = __expf(a[k] - mx); s += a[k]; }
        float inv = 1.f / s;
        #pragma unroll
        for (int k = 0; k < 9; k++) a[k] *= inv;
    }
    __syncthreads();

    // ---- combine: out[c] = sum_k a[k] * v[c] at neighbor k ----
    {
        int hpk[9];
        #pragma unroll
        for (int k = 0; k < 9; k++) {
            int i = k / 3, j = k - i * 3;
            hpk[k] = ((ty + i) * 18 + (tx + j)) * 36;
        }
        float* ob = out + ((size_t)img * 256 + g * 32) * 16384 + px;
        #pragma unroll
        for (int c4 = 0; c4 < 8; c4++) {
            float ax = 0.f, ay = 0.f, az = 0.f, aw = 0.f;
            #pragma unroll
            for (int k = 0; k < 9; k++) {
                float4 vv = *(const float4*)(s_v + hpk[k] + c4 * 4);
                ax += a[k] * vv.x; ay += a[k] * vv.y;
                az += a[k] * vv.z; aw += a[k] * vv.w;
            }
            ob[(size_t)(c4 * 4 + 0) * 16384] = ax;
            ob[(size_t)(c4 * 4 + 1) * 16384] = ay;
            ob[(size_t)(c4 * 4 + 2) * 16384] = az;
            ob[(size_t)(c4 * 4 + 3) * 16384] = aw;
        }
    }
}

extern "C" void kernel_launch(void* const* d_in, const int* in_sizes, int n_in,
                              void* d_out, int out_size) {
    const float* x   = (const float*)d_in[0];
    const float* w1  = (const float*)d_in[1];
    const float* b1  = (const float*)d_in[2];
    const float* g1  = (const float*)d_in[3];
    const float* be1 = (const float*)d_in[4];
    const float* m1  = (const float*)d_in[5];
    const float* v1  = (const float*)d_in[6];
    const float* w2  = (const float*)d_in[7];
    const float* b2  = (const float*)d_in[8];
    const float* g2  = (const float*)d_in[9];
    const float* be2 = (const float*)d_in[10];
    const float* m2  = (const float*)d_in[11];
    const float* v2  = (const float*)d_in[12];
    const float* wv  = (const float*)d_in[13];
    float* out = (float*)d_out;

    stage1_kernel<<<dim3(64, 8, 2), 256>>>(x, w1, b1, g1, be1, m1, v1,
                                           w2, b2, g2, be2, m2, v2, wv);
    combine_kernel<<<dim3(8, 8, 16), 256>>>(out);
}

// round 12
// speedup vs baseline: 1.5678x; 1.0316x over previous
#include <cuda_runtime.h>
#include <cuda_fp16.h>

// LocalAttn, 2-kernel pipeline for GB300 (sm_103a), round 12.
// = round-11 (best, 53.3us) + g_mn stored fp16 + combine gathers v via 16B loads.
// Kernel A (stage1): coalesced LDG.64 x staging into quad-swizzled smem rows,
//   x row -> registers, mn = bn2(conv2(ftanh(bn1(conv1 x)))) -> g_mn (fp16),
//   v = wv @ x -> own swizzled smem row -> coalesced fp16 STG -> g_v.
// Kernel M (combine): gather fp16 v halo (16B uint4 loads), convert to fp32 smem,
//   softmax(mask+nb from fp16 g_mn) in regs, combine, write out fp32.

typedef unsigned long long ull;

__device__ __half g_v [2u * 8u * 16384u * 32u]; // [img][g][px][32]  16.8 MB
__device__ __half g_mn[2u * 80u * 16384u];      // [img][ch][px]      5.2 MB

__device__ __forceinline__ ull fma2(ull a, ull b, ull c) {
    ull d;
    asm("fma.rn.f32x2 %0, %1, %2, %3;" : "=l"(d) : "l"(a), "l"(b), "l"(c));
    return d;
}
__device__ __forceinline__ float hadd2(ull a) {
    float x, y;
    asm("mov.b64 {%0,%1}, %2;" : "=f"(x), "=f"(y) : "l"(a));
    return x + y;
}
__device__ __forceinline__ float ftanh(float x) {
    float e = __expf(-2.f * fabsf(x));
    float r = __fdividef(1.f - e, 1.f + e);
    return copysignf(r, x);
}

// ============================ Kernel A ============================
// grid (64, 8, 2) = (px chunk, group, img), block 256, one thread per pixel.
// smem x layout: word = px*36 + ((q ^ ((px>>3)&7))<<2) + w   (c = 4q + w)
__global__ __launch_bounds__(256, 3)
void stage1_kernel(
    const float* __restrict__ x,
    const float* __restrict__ w1, const float* __restrict__ b1,
    const float* __restrict__ g1, const float* __restrict__ be1,
    const float* __restrict__ m1, const float* __restrict__ v1,
    const float* __restrict__ w2, const float* __restrict__ b2,
    const float* __restrict__ g2, const float* __restrict__ be2,
    const float* __restrict__ m2, const float* __restrict__ v2,
    const float* __restrict__ wv)
{
    __shared__ __align__(16) float s_px[256 * 36];   // swizzled [px][ci]; later v
    __shared__ __align__(16) float s_w1g[256];       // w1[g]  (8,32)
    __shared__ __align__(16) float s_wvg[1024];      // wv[g]  (32,32)
    __shared__ __align__(16) float s_w2g[80];        // w2[g]  (10,8)
    __shared__ float s_a1[8], s_c1[8], s_a2[10], s_c2[10];

    const int t    = threadIdx.x;
    const int lane = t & 31;
    const int wq   = t >> 5;
    const int px0  = blockIdx.x * 256;
    const int g    = blockIdx.y;
    const int img  = blockIdx.z;

    // weights + folded BN params
    s_w1g[t] = w1[g * 256 + t];
    for (int i = t; i < 1024; i += 256) s_wvg[i] = wv[g * 1024 + i];
    if (t < 80) s_w2g[t] = w2[g * 80 + t];
    if (t < 8) {
        int ch = g * 8 + t;
        float inv = g1[ch] * rsqrtf(v1[ch] + 1e-5f);
        s_a1[t] = inv;
        s_c1[t] = b1[ch] * inv + be1[ch] - m1[ch] * inv;
    } else if (t >= 32 && t < 42) {
        int o = t - 32, ch = g * 10 + o;
        float inv = g2[ch] * rsqrtf(v2[ch] + 1e-5f);
        s_a2[o] = inv;
        s_c2[o] = b2[ch] * inv + be2[ch] - m2[ch] * inv;
    }

    // ---- coalesced x staging: warp wq handles channels [wq*4, wq*4+4) ----
    {
        const float* xg = x + ((size_t)img * 256 + g * 32) * 16384 + px0;
        #pragma unroll
        for (int it = 0; it < 4; ++it) {
            int c = wq * 4 + it;
            int q = c >> 2, wrd = c & 3;
            const float* src = xg + (size_t)c * 16384;
            #pragma unroll
            for (int seg = 0; seg < 4; ++seg) {
                int p = (lane + seg * 32) * 2;           // even pixel
                float2 v2 = *(const float2*)(src + p);
                int qs = ((q ^ ((p >> 3) & 7)) << 2) + wrd;
                s_px[p * 36 + qs]       = v2.x;
                s_px[(p + 1) * 36 + qs] = v2.y;
            }
        }
    }
    __syncthreads();

    // pull own x row into registers (logical quad order, physical swizzled)
    const int sw = (t >> 3) & 7;
    float* xrow = s_px + t * 36;
    ulonglong2 xr[8];
    #pragma unroll
    for (int q = 0; q < 8; q++)
        xr[q] = *(const ulonglong2*)(xrow + ((q ^ sw) << 2));

    // ---- conv1 -> bn -> tanh -> conv2 -> bn -> g_mn (fp16) ----
    {
        ull acc[8];
        #pragma unroll
        for (int o = 0; o < 8; o++) acc[o] = 0ULL;
        #pragma unroll
        for (int q = 0; q < 8; q++) {
            #pragma unroll
            for (int o = 0; o < 8; o++) {
                ulonglong2 wp = *(const ulonglong2*)(s_w1g + o * 32 + q * 4);
                acc[o] = fma2(xr[q].x, wp.x, acc[o]);
                acc[o] = fma2(xr[q].y, wp.y, acc[o]);
            }
        }
        float tv[8];
        #pragma unroll
        for (int o = 0; o < 8; o++)
            tv[o] = ftanh(hadd2(acc[o]) * s_a1[o] + s_c1[o]);

        __half* mb = g_mn + ((size_t)img * 80 + g * 10) * 16384 + px0 + t;
        #pragma unroll
        for (int o2 = 0; o2 < 10; o2++) {
            float a = 0.f;
            #pragma unroll
            for (int o = 0; o < 8; o++) a += tv[o] * s_w2g[o2 * 8 + o];
            mb[(size_t)o2 * 16384] = __float2half_rn(a * s_a2[o2] + s_c2[o2]);
        }
    }

    // ---- v = wv @ x in 4 chunks of 8 outputs; write into own swizzled row ----
    #pragma unroll
    for (int ch = 0; ch < 4; ch++) {
        ull acc[8];
        #pragma unroll
        for (int o = 0; o < 8; o++) acc[o] = 0ULL;
        #pragma unroll
        for (int q = 0; q < 8; q++) {
            #pragma unroll
            for (int o = 0; o < 8; o++) {
                ulonglong2 wp = *(const ulonglong2*)(s_wvg + (ch * 8 + o) * 32 + q * 4);
                acc[o] = fma2(xr[q].x, wp.x, acc[o]);
                acc[o] = fma2(xr[q].y, wp.y, acc[o]);
            }
        }
        float4 r;
        r.x = hadd2(acc[0]); r.y = hadd2(acc[1]);
        r.z = hadd2(acc[2]); r.w = hadd2(acc[3]);
        *(float4*)(xrow + (((2 * ch)     ^ sw) << 2)) = r;
        r.x = hadd2(acc[4]); r.y = hadd2(acc[5]);
        r.z = hadd2(acc[6]); r.w = hadd2(acc[7]);
        *(float4*)(xrow + (((2 * ch + 1) ^ sw) << 2)) = r;
    }
    __syncthreads();

    // ---- coalesced fp16 store of v: warp writes 256B contiguous ----
    __half* vplane = g_v + ((size_t)(img * 8 + g) * 16384 + px0) * 32;
    #pragma unroll
    for (int i = 0; i < 8; i++) {
        int idx = t + i * 256;          // 2048 4-channel items
        int p = idx >> 3, q = idx & 7;
        int sp = (p >> 3) & 7;
        float4 v4 = *(const float4*)(s_px + p * 36 + ((q ^ sp) << 2));
        __half2 h0 = __floats2half2_rn(v4.x, v4.y);
        __half2 h1 = __floats2half2_rn(v4.z, v4.w);
        uint2 st;
        st.x = *(unsigned int*)&h0;
        st.y = *(unsigned int*)&h1;
        *(uint2*)(vplane + p * 32 + q * 4) = st;
    }
}

// ============================ Kernel M ============================
// grid (8, 8, 16): z = img*8 + g. block 256 (one thread per center pixel).
__global__ __launch_bounds__(256, 4)
void combine_kernel(float* __restrict__ out)
{
    __shared__ __align__(16) float s_v[324 * 36];   // [hp][co] pitch 36 (fp32)

    const int t   = threadIdx.x;
    const int ty  = t >> 4, tx = t & 15;
    const int w0  = blockIdx.x * 16;
    const int h0  = blockIdx.y * 16;
    const int img = blockIdx.z >> 3;
    const int g   = blockIdx.z & 7;
    const int h   = h0 + ty, w = w0 + tx;
    const int px  = h * 128 + w;

    // ---- v halo gather: 16B loads (8 fp16 channels per item) ----
    const __half* vt = g_v + (size_t)(img * 8 + g) * (16384u * 32u);
    #pragma unroll
    for (int i = 0; i < 6; i++) {
        int idx = t + i * 256;          // 1296 items = 324 px * 4 chunks of 8ch
        if (idx < 1296) {
            int hp = idx >> 2, q = idx & 3;
            int hy = hp / 18, hx = hp - hy * 18;
            int hh = h0 + hy - 1, ww = w0 + hx - 1;
            uint4 raw = make_uint4(0u, 0u, 0u, 0u);
            if (((unsigned)hh < 128u) & ((unsigned)ww < 128u))
                raw = *(const uint4*)(vt + (size_t)(hh * 128 + ww) * 32 + q * 8);
            float2 f0 = __half22float2(*(__half2*)&raw.x);
            float2 f1 = __half22float2(*(__half2*)&raw.y);
            float2 f2 = __half22float2(*(__half2*)&raw.z);
            float2 f3 = __half22float2(*(__half2*)&raw.w);
            float* dst = s_v + hp * 36 + q * 8;
            *(float4*)(dst)     = make_float4(f0.x, f0.y, f1.x, f1.y);
            *(float4*)(dst + 4) = make_float4(f2.x, f2.y, f3.x, f3.y);
        }
    }

    // ---- logits: mask (9 strided coalesced) + neighbor (9 predicated), fp16 ----
    float a[9];
    {
        const __half* nbg   = g_mn + ((size_t)img * 80 + g) * 16384;
        const __half* mbase = g_mn + ((size_t)img * 80 + 8 + g * 9) * 16384 + px;
        #pragma unroll
        for (int k = 0; k < 9; k++) {
            int i = k / 3, j = k - i * 3;
            int hh = h + i - 1, ww = w + j - 1;
            float nb = 0.f;
            if (((unsigned)hh < 128u) & ((unsigned)ww < 128u))
                nb = __half2float(nbg[hh * 128 + ww]);
            a[k] = __half2float(mbase[(size_t)k * 16384]) + nb;
        }
        float mx = a[0];
        #pragma unroll
        for (int k = 1; k < 9; k++) mx = fmaxf(mx, a[k]);
        float s = 0.f;
        #pragma unroll
        for (int k = 0; k < 9; k++) { a[k] = __expf(a[k] - mx); s += a[k]; }
        float inv = 1.f / s;
        #pragma unroll
        for (int k = 0; k < 9; k++) a[k] *= inv;
    }
    __syncthreads();

    // ---- combine: out[c] = sum_k a[k] * v[c] at neighbor k ----
    {
        int hpk[9];
        #pragma unroll
        for (int k = 0; k < 9; k++) {
            int i = k / 3, j = k - i * 3;
            hpk[k] = ((ty + i) * 18 + (tx + j)) * 36;
        }
        float* ob = out + ((size_t)img * 256 + g * 32) * 16384 + px;
        #pragma unroll
        for (int c4 = 0; c4 < 8; c4++) {
            float ax = 0.f, ay = 0.f, az = 0.f, aw = 0.f;
            #pragma unroll
            for (int k = 0; k < 9; k++) {
                float4 vv = *(const float4*)(s_v + hpk[k] + c4 * 4);
                ax += a[k] * vv.x; ay += a[k] * vv.y;
                az += a[k] * vv.z; aw += a[k] * vv.w;
            }
            ob[(size_t)(c4 * 4 + 0) * 16384] = ax;
            ob[(size_t)(c4 * 4 + 1) * 16384] = ay;
            ob[(size_t)(c4 * 4 + 2) * 16384] = az;
            ob[(size_t)(c4 * 4 + 3) * 16384] = aw;
        }
    }
}

extern "C" void kernel_launch(void* const* d_in, const int* in_sizes, int n_in,
                              void* d_out, int out_size) {
    const float* x   = (const float*)d_in[0];
    const float* w1  = (const float*)d_in[1];
    const float* b1  = (const float*)d_in[2];
    const float* g1  = (const float*)d_in[3];
    const float* be1 = (const float*)d_in[4];
    const float* m1  = (const float*)d_in[5];
    const float* v1  = (const float*)d_in[6];
    const float* w2  = (const float*)d_in[7];
    const float* b2  = (const float*)d_in[8];
    const float* g2  = (const float*)d_in[9];
    const float* be2 = (const float*)d_in[10];
    const float* m2  = (const float*)d_in[11];
    const float* v2  = (const float*)d_in[12];
    const float* wv  = (const float*)d_in[13];
    float* out = (float*)d_out;

    stage1_kernel<<<dim3(64, 8, 2), 256>>>(x, w1, b1, g1, be1, m1, v1,
                                           w2, b2, g2, be2, m2, v2, wv);
    combine_kernel<<<dim3(8, 8, 16), 256>>>(out);
}